// round 4
// baseline (speedup 1.0000x reference)
#include <cuda_runtime.h>
#include <cuda_bf16.h>
#include <math.h>

// ---------------- problem constants ----------------
#define B_   128
#define C_   256
#define LW   256     // words = L-1
#define T_   1024
#define NH   8
#define NP   8
#define NLAY 3

// ---------------- scratch (device globals; no runtime allocation) ----------------
__device__ float g_word_pe[B_*LW*C_];      // 32 MB
__device__ float g_wp     [B_*LW*C_];      // 32 MB
__device__ float g_vproj  [B_*T_*C_];      // 128 MB
__device__ float g_sim    [B_*LW*T_];      // 128 MB
__device__ float g_entropy[B_*LW];
__device__ float g_Kbuf   [B_*LW*C_];      // 32 MB (reused per layer)
__device__ float g_Vbuf   [B_*LW*C_];      // 32 MB (reused per layer)
__device__ float g_Wq[NLAY*C_*C_];
__device__ float g_Wk[NLAY*C_*C_];
__device__ float g_Wv[NLAY*C_*C_];
__device__ float g_bq[NLAY*C_];
__device__ float g_bk[NLAY*C_];
__device__ float g_bv[NLAY*C_];
__device__ float g_x0[B_*NP*C_];
__device__ float g_x1[B_*NP*C_];
__device__ float g_O [B_*NP*C_];
__device__ float g_attn3[B_*NH*NP*LW];     // 2 MB (last-layer attn for slot_sim)

// ---------------- reduction helpers ----------------
__device__ __forceinline__ float warpSum(float v){
#pragma unroll
    for (int o = 16; o > 0; o >>= 1) v += __shfl_xor_sync(0xffffffffu, v, o);
    return v;
}
__device__ __forceinline__ float warpMax(float v){
#pragma unroll
    for (int o = 16; o > 0; o >>= 1) v = fmaxf(v, __shfl_xor_sync(0xffffffffu, v, o));
    return v;
}
// 256-thread block reductions; sh is caller-provided __shared__ float[8]
__device__ __forceinline__ float blockSum256(float v, float* sh){
    int lane = threadIdx.x & 31, w = threadIdx.x >> 5;
    v = warpSum(v);
    __syncthreads();
    if (lane == 0) sh[w] = v;
    __syncthreads();
    float t = sh[0];
#pragma unroll
    for (int i = 1; i < 8; i++) t += sh[i];
    return t;
}
__device__ __forceinline__ float blockMax256(float v, float* sh){
    int lane = threadIdx.x & 31, w = threadIdx.x >> 5;
    v = warpMax(v);
    __syncthreads();
    if (lane == 0) sh[w] = v;
    __syncthreads();
    float t = sh[0];
#pragma unroll
    for (int i = 1; i < 8; i++) t = fmaxf(t, sh[i]);
    return t;
}

// ---------------- word_pe = txt_emb[:,1:] + sine positional ----------------
__global__ void k_word_pe(const float* __restrict__ txt_emb, float* __restrict__ wpe){
    int idx = blockIdx.x * 256 + threadIdx.x;   // B_*LW*C_ total
    int c = idx & 255;
    int l = (idx >> 8) & 255;
    int b = idx >> 16;
    float x = (float)(l + 1);                   // cumsum of all-ones mask
    float expo = (float)(c & ~1) * (1.0f / 256.0f);
    float d = expf(expo * 9.210340371976184f);  // 10000^(2*floor(c/2)/256)
    float arg = x / d;
    float pe = (c & 1) ? cosf(arg) : sinf(arg);
    wpe[idx] = txt_emb[((size_t)b * 257 + (l + 1)) * 256 + c] + pe;
}

// ---------------- generic batched SGEMM 128x128x8, 256 threads ----------------
// C[b] = A[b](MxK) * op(B[b]) + bias ; NN: B is KxN row-major; NT: B is NxK row-major.
// All M,N multiples of 128; K multiple of 8.
// Register-prefetch double buffering: next k-tile's LDGs issue before the
// compute phase so their latency overlaps the 8 k-step FFMA block.
template<bool TRANSB>
__global__ void __launch_bounds__(256, 2) k_sgemm(
    const float* __restrict__ A, int lda, long long sA,
    const float* __restrict__ B, int ldb, long long sB,
    const float* __restrict__ bias,
    float* __restrict__ C, int ldc, long long sC, int K)
{
    __shared__ float As[8][128];
    __shared__ float Bs[8][128];
    const int tid = threadIdx.x;
    const int ntile = blockIdx.x * 128;

    const float* Ab = A + (long long)blockIdx.z * sA + (long long)(blockIdx.y * 128) * lda;
    const float* Bb = B + (long long)blockIdx.z * sB;
    float*       Cb = C + (long long)blockIdx.z * sC + (long long)(blockIdx.y * 128) * ldc + ntile;

    const int arow = tid >> 1;            // 0..127
    const int acol = (tid & 1) * 4;       // 0 or 4
    const int brow = tid >> 5;            // 0..7   (NN)
    const int bcol = (tid & 31) * 4;      // 0..124 (NN)
    const int tx = (tid & 15) * 4;        // col base
    const int ty = (tid >> 4) * 4;        // row base

    float acc[8][8];
#pragma unroll
    for (int i = 0; i < 8; i++)
#pragma unroll
        for (int j = 0; j < 8; j++) acc[i][j] = 0.f;

    // prologue: load first k-tile into registers
    float4 av = *(const float4*)(Ab + (long long)arow * lda + acol);
    float4 bv;
    if (TRANSB) bv = *(const float4*)(Bb + (long long)(ntile + arow) * ldb + acol);
    else        bv = *(const float4*)(Bb + (long long)brow * ldb + ntile + bcol);

    for (int k0 = 0; k0 < K; k0 += 8){
        // stage current tile to smem
        As[acol+0][arow] = av.x; As[acol+1][arow] = av.y;
        As[acol+2][arow] = av.z; As[acol+3][arow] = av.w;
        if (TRANSB){
            Bs[acol+0][arow] = bv.x; Bs[acol+1][arow] = bv.y;
            Bs[acol+2][arow] = bv.z; Bs[acol+3][arow] = bv.w;
        } else {
            *(float4*)(&Bs[brow][bcol]) = bv;
        }
        __syncthreads();

        // prefetch next tile (overlaps with compute below)
        const int kn = k0 + 8;
        if (kn < K){
            av = *(const float4*)(Ab + (long long)arow * lda + kn + acol);
            if (TRANSB) bv = *(const float4*)(Bb + (long long)(ntile + arow) * ldb + kn + acol);
            else        bv = *(const float4*)(Bb + (long long)(kn + brow) * ldb + ntile + bcol);
        }

#pragma unroll
        for (int k = 0; k < 8; k++){
            float a0[8], b0[8];
            *(float4*)(a0)     = *(const float4*)(&As[k][ty]);
            *(float4*)(a0 + 4) = *(const float4*)(&As[k][ty + 64]);
            *(float4*)(b0)     = *(const float4*)(&Bs[k][tx]);
            *(float4*)(b0 + 4) = *(const float4*)(&Bs[k][tx + 64]);
#pragma unroll
            for (int i = 0; i < 8; i++)
#pragma unroll
                for (int j = 0; j < 8; j++)
                    acc[i][j] += a0[i] * b0[j];
        }
        __syncthreads();
    }

    float bvals[8];
    if (bias){
#pragma unroll
        for (int j = 0; j < 4; j++){ bvals[j] = bias[ntile + tx + j]; bvals[j+4] = bias[ntile + tx + 64 + j]; }
    } else {
#pragma unroll
        for (int j = 0; j < 8; j++) bvals[j] = 0.f;
    }
#pragma unroll
    for (int i = 0; i < 8; i++){
        int m = (i < 4) ? (ty + i) : (ty + 64 + (i - 4));
        float* cp = Cb + (long long)m * ldc;
        float4 v0 = make_float4(acc[i][0]+bvals[0], acc[i][1]+bvals[1], acc[i][2]+bvals[2], acc[i][3]+bvals[3]);
        float4 v1 = make_float4(acc[i][4]+bvals[4], acc[i][5]+bvals[5], acc[i][6]+bvals[6], acc[i][7]+bvals[7]);
        *(float4*)(cp + tx)      = v0;
        *(float4*)(cp + tx + 64) = v1;
    }
}

// ---------------- combined biases: b' = b_small @ in_w_slice + in_b_slice ----------------
__global__ void k_bias_combine(const float* __restrict__ q_b, const float* __restrict__ kv_b,
                               const float* __restrict__ in_w, const float* __restrict__ in_b,
                               float* __restrict__ bq, float* __restrict__ bk, float* __restrict__ bv)
{
    int i = blockIdx.x / 3, type = blockIdx.x % 3;
    int c = threadIdx.x;
    const float* inw = in_w + (size_t)i * 256 * 768;
    const float* inb = in_b + (size_t)i * 768;
    float acc;
    if (type == 0){
        acc = inb[c];
        for (int j = 0; j < 256; j++) acc += q_b[i*256 + j] * inw[j*768 + c];
        bq[i*256 + c] = acc;
    } else if (type == 1){
        acc = inb[256 + c];
        for (int j = 0; j < 256; j++) acc += kv_b[i*512 + j] * inw[j*768 + 256 + c];
        bk[i*256 + c] = acc;
    } else {
        acc = inb[512 + c];
        for (int j = 0; j < 256; j++) acc += kv_b[i*512 + 256 + j] * inw[j*768 + 512 + c];
        bv[i*256 + c] = acc;
    }
}

// ---------------- fused softmax over T + entropy (row = b*LW + l) ----------------
__global__ void __launch_bounds__(256) k_softmax_entropy(
    const float* __restrict__ sim, float* __restrict__ attn, float* __restrict__ ent)
{
    __shared__ float sh[8];
    int row = blockIdx.x;
    int t = threadIdx.x;
    const float4 v = ((const float4*)(sim + (size_t)row * 1024))[t];
    float m = fmaxf(fmaxf(v.x, v.y), fmaxf(v.z, v.w));
    m = blockMax256(m, sh);
    float ex = expf(v.x - m), ey = expf(v.y - m), ez = expf(v.z - m), ew = expf(v.w - m);
    float s = blockSum256(ex + ey + ez + ew, sh);
    float inv = 1.0f / s;
    float4 p = make_float4(ex*inv, ey*inv, ez*inv, ew*inv);
    ((float4*)(attn + (size_t)row * 1024))[t] = p;
    float e = p.x * logf(p.x + 1e-6f) + p.y * logf(p.y + 1e-6f)
            + p.z * logf(p.z + 1e-6f) + p.w * logf(p.w + 1e-6f);
    e = blockSum256(e, sh);
    if (t == 0) ent[row] = -e;
}

// ---------------- per-batch selection (stable desc sort + greedy) + gather ----------------
__global__ void __launch_bounds__(256) k_select_gather(
    const float* __restrict__ ent, const float* __restrict__ wpe, float* __restrict__ x0)
{
    __shared__ unsigned long long key[256];
    __shared__ int ssel[NP];
    int b = blockIdx.x;
    int t = threadIdx.x;
    float s = ent[b*256 + t];
    unsigned u = __float_as_uint(s);
    u = (u & 0x80000000u) ? ~u : (u ^ 0x80000000u);           // ascending-monotonic
    key[t] = ((unsigned long long)(~u) << 32) | (unsigned long long)t;  // asc sort => desc score, ties asc idx
    __syncthreads();
    for (int k = 2; k <= 256; k <<= 1){
        for (int j = k >> 1; j > 0; j >>= 1){
            int ixj = t ^ j;
            if (ixj > t){
                unsigned long long a = key[t], c2 = key[ixj];
                bool up = ((t & k) == 0);
                if ((a > c2) == up){ key[t] = c2; key[ixj] = a; }
            }
            __syncthreads();
        }
    }
    if (t == 0){
        int sel[NP]; int cnt = 0;
        for (int r = 0; r < 256 && cnt < NP; r++){
            int idx = (int)(key[r] & 0xffffffffULL);
            bool ok = true;
            for (int j2 = 0; j2 < cnt; j2++){
                int dd = idx - sel[j2]; if (dd < 0) dd = -dd;
                if (dd < 2){ ok = false; break; }
            }
            if (ok) sel[cnt++] = idx;
        }
        int last = sel[(cnt > 0) ? cnt - 1 : 0];
        for (int p = 0; p < NP; p++) ssel[p] = (p < cnt) ? sel[p] : last;
    }
    __syncthreads();
    for (int i = t; i < NP*C_; i += 256){
        int p = i >> 8, cc = i & 255;
        x0[(size_t)b * NP * C_ + i] = wpe[((size_t)b * 256 + ssel[p]) * 256 + cc];
    }
}

// ---------------- attention per (b,h): Q-proj + scores + softmax + O ----------------
__global__ void __launch_bounds__(256) k_attn(
    const float* __restrict__ x, const float* __restrict__ Wq, const float* __restrict__ bq,
    const float* __restrict__ Kb, const float* __restrict__ Vb,
    float* __restrict__ O, float* __restrict__ attn3)
{
    __shared__ float sXV[8192];   // first: x[b] (2048), then V head slice (8192)
    __shared__ float sQ[NP*32];
    __shared__ float sS[NP*256];
    int blk = blockIdx.x;
    int b = blk >> 3, h = blk & 7;
    int tid = threadIdx.x;
    for (int i = tid; i < NP*C_; i += 256) sXV[i] = x[(size_t)b * NP * C_ + i];
    __syncthreads();
    int q = tid >> 5, d = tid & 31;
    int col = h * 32 + d;
    float acc = bq[col];
#pragma unroll 4
    for (int j = 0; j < 256; j++) acc += sXV[q*256 + j] * Wq[j*256 + col];
    __syncthreads();
    sQ[q*32 + d] = acc * 0.17677669529663687f;   // 1/sqrt(32)
    __syncthreads();
    const float* Kp = Kb + (size_t)b * LW * C_;
    const float* Vp = Vb + (size_t)b * LW * C_;
    for (int i = tid; i < LW*32; i += 256){
        int r = i >> 5, cc = i & 31;
        sXV[i] = Vp[r*256 + h*32 + cc];
    }
    {   // scores: thread = key index
        int k = tid;
        const float4* kp = (const float4*)(Kp + (size_t)k * 256 + h * 32);
        float4 kr[8];
#pragma unroll
        for (int j = 0; j < 8; j++) kr[j] = kp[j];
#pragma unroll
        for (int qq = 0; qq < NP; qq++){
            const float4* qp4 = (const float4*)(sQ + qq * 32);
            float sc = 0.f;
#pragma unroll
            for (int j = 0; j < 8; j++){
                float4 qv = qp4[j];
                sc += qv.x*kr[j].x + qv.y*kr[j].y + qv.z*kr[j].z + qv.w*kr[j].w;
            }
            sS[qq*256 + k] = sc;
        }
    }
    __syncthreads();
    {   // softmax over k: warp q owns row q
        float m = -INFINITY;
#pragma unroll
        for (int k = d; k < 256; k += 32) m = fmaxf(m, sS[q*256 + k]);
        m = warpMax(m);
        float sum = 0.f;
#pragma unroll
        for (int k = d; k < 256; k += 32){ float e = expf(sS[q*256 + k] - m); sS[q*256 + k] = e; sum += e; }
        sum = warpSum(sum);
        float inv = 1.0f / sum;
#pragma unroll
        for (int k = d; k < 256; k += 32) sS[q*256 + k] *= inv;
    }
    __syncthreads();
    float o_ = 0.f;
#pragma unroll 8
    for (int k = 0; k < 256; k++) o_ += sS[q*256 + k] * sXV[k*32 + d];
    O[(size_t)b * NP * C_ + q * 256 + col] = o_;
    if (attn3){
        int k = tid;
#pragma unroll
        for (int qq = 0; qq < NP; qq++)
            attn3[(size_t)b * (NH*NP*LW) + h * (NP*LW) + qq * LW + k] = sS[qq*256 + k];
    }
}

// ---------------- per-row: out-proj + residual + LN + FFN(relu) + residual + LN ----------------
__global__ void __launch_bounds__(256) k_post(
    const float* __restrict__ x, const float* __restrict__ O,
    const float* __restrict__ ow, const float* __restrict__ ob,
    const float* __restrict__ g0, const float* __restrict__ b0,
    const float* __restrict__ lw, const float* __restrict__ lb,
    const float* __restrict__ g1, const float* __restrict__ b1,
    float* __restrict__ xout)
{
    __shared__ float sO[256];
    __shared__ float sX1[256];
    __shared__ float sh[8];
    int row = blockIdx.x;
    int c = threadIdx.x;
    sO[c] = O[(size_t)row * 256 + c];
    float xv = x[(size_t)row * 256 + c];
    __syncthreads();
    float acc = ob[c];
#pragma unroll 4
    for (int j = 0; j < 256; j++) acc += sO[j] * ow[j*256 + c];
    float a = xv + acc;
    float mu = blockSum256(a, sh) * (1.0f/256.0f);
    float tdev = a - mu;
    float var = blockSum256(tdev*tdev, sh) * (1.0f/256.0f);
    float x1 = tdev * rsqrtf(var + 1e-5f) * g0[c] + b0[c];
    sX1[c] = x1;
    __syncthreads();
    float u = lb[c];
#pragma unroll 4
    for (int j = 0; j < 256; j++) u += sX1[j] * lw[j*256 + c];
    u = fmaxf(u, 0.0f);
    float a2 = x1 + u;
    float mu2 = blockSum256(a2, sh) * (1.0f/256.0f);
    float t2 = a2 - mu2;
    float var2 = blockSum256(t2*t2, sh) * (1.0f/256.0f);
    xout[(size_t)row * 256 + c] = t2 * rsqrtf(var2 + 1e-5f) * g1[c] + b1[c];
}

// ---------------- slot_sim = mean over heads of last-layer attn ----------------
__global__ void k_slot_sim(const float* __restrict__ attn3, float* __restrict__ out){
    int idx = blockIdx.x * 256 + threadIdx.x;     // B_*NP*LW total
    int b = idx >> 11;                             // / (NP*LW)
    int r = idx & 2047;                            // q*256+k
    float s = 0.f;
#pragma unroll
    for (int h = 0; h < NH; h++) s += attn3[(size_t)b * (NH*NP*LW) + h * (NP*LW) + r];
    out[idx] = s * (1.0f / NH);
}

// ---------------- eos broadcast ----------------
__global__ void k_eos(const float* __restrict__ eos, float* __restrict__ out){
    out[blockIdx.x * 256 + threadIdx.x] = eos[threadIdx.x];
}

// ================= host launcher =================
extern "C" void kernel_launch(void* const* d_in, const int* in_sizes, int n_in,
                              void* d_out, int out_size)
{
    const float* txt_emb      = (const float*)d_in[0];
    const float* video_feats  = (const float*)d_in[2];
    const float* word_proj_w  = (const float*)d_in[4];
    const float* word_proj_b  = (const float*)d_in[5];
    const float* video_proj_w = (const float*)d_in[6];
    const float* video_proj_b = (const float*)d_in[7];
    const float* q_w   = (const float*)d_in[8];
    const float* q_b   = (const float*)d_in[9];
    const float* kv_w  = (const float*)d_in[10];
    const float* kv_b  = (const float*)d_in[11];
    const float* in_w  = (const float*)d_in[12];
    const float* in_b  = (const float*)d_in[13];
    const float* out_w = (const float*)d_in[14];
    const float* out_b = (const float*)d_in[15];
    const float* ln0_g = (const float*)d_in[16];
    const float* ln0_b = (const float*)d_in[17];
    const float* lin_w = (const float*)d_in[18];
    const float* lin_b = (const float*)d_in[19];
    const float* ln1_g = (const float*)d_in[20];
    const float* ln1_b = (const float*)d_in[21];
    const float* eos_slot = (const float*)d_in[22];

    float *wpe, *wp, *vproj, *sim, *ent, *Kb, *Vb, *Wq, *Wk, *Wv, *bq, *bk, *bv, *x0, *x1, *O, *attn3;
    cudaGetSymbolAddress((void**)&wpe,   g_word_pe);
    cudaGetSymbolAddress((void**)&wp,    g_wp);
    cudaGetSymbolAddress((void**)&vproj, g_vproj);
    cudaGetSymbolAddress((void**)&sim,   g_sim);
    cudaGetSymbolAddress((void**)&ent,   g_entropy);
    cudaGetSymbolAddress((void**)&Kb,    g_Kbuf);
    cudaGetSymbolAddress((void**)&Vb,    g_Vbuf);
    cudaGetSymbolAddress((void**)&Wq,    g_Wq);
    cudaGetSymbolAddress((void**)&Wk,    g_Wk);
    cudaGetSymbolAddress((void**)&Wv,    g_Wv);
    cudaGetSymbolAddress((void**)&bq,    g_bq);
    cudaGetSymbolAddress((void**)&bk,    g_bk);
    cudaGetSymbolAddress((void**)&bv,    g_bv);
    cudaGetSymbolAddress((void**)&x0,    g_x0);
    cudaGetSymbolAddress((void**)&x1,    g_x1);
    cudaGetSymbolAddress((void**)&O,     g_O);
    cudaGetSymbolAddress((void**)&attn3, g_attn3);

    float* out = (float*)d_out;
    float* out_phrase  = out;                         // [128,8,256]
    float* out_attn    = out + 262144;                // [128,256,1024]
    float* out_slotsim = out + 33816576;              // [128,8,256]
    float* out_eos     = out + 34078720;              // [128,1,256]

    // 1) word positional embedding
    k_word_pe<<<B_*LW*C_/256, 256>>>(txt_emb, wpe);

    // 2) combined per-layer weights:  Wq=qw@inw_q, Wk=kvw_k@inw_k, Wv=kvw_v@inw_v
    for (int i = 0; i < NLAY; i++){
        k_sgemm<false><<<dim3(2,2,1), 256>>>(q_w  + (size_t)i*65536,        256, 0,
                                             in_w + (size_t)i*196608,       768, 0, nullptr,
                                             Wq + (size_t)i*65536, 256, 0, 256);
        k_sgemm<false><<<dim3(2,2,1), 256>>>(kv_w + (size_t)i*131072,       512, 0,
                                             in_w + (size_t)i*196608 + 256, 768, 0, nullptr,
                                             Wk + (size_t)i*65536, 256, 0, 256);
        k_sgemm<false><<<dim3(2,2,1), 256>>>(kv_w + (size_t)i*131072 + 256, 512, 0,
                                             in_w + (size_t)i*196608 + 512, 768, 0, nullptr,
                                             Wv + (size_t)i*65536, 256, 0, 256);
    }
    k_bias_combine<<<9, 256>>>(q_b, kv_b, in_w, in_b, bq, bk, bv);

    // 3) projections
    k_sgemm<false><<<dim3(2,2,B_), 256>>>(wpe, 256, 65536, word_proj_w, 256, 0, word_proj_b,
                                          wp, 256, 65536, 256);
    k_sgemm<false><<<dim3(2,8,B_), 256>>>(video_feats, 256, 262144, video_proj_w, 256, 0, video_proj_b,
                                          vproj, 256, 262144, 256);

    // 4) sim = wp @ vproj^T   (NT)
    k_sgemm<true><<<dim3(8,2,B_), 256>>>(wp, 256, 65536, vproj, 256, 262144, nullptr,
                                         sim, 1024, 262144, 256);

    // 5) softmax over T -> attn output, entropy
    k_softmax_entropy<<<B_*LW, 256>>>(sim, out_attn, ent);

    // 6) selection + gather phrase slots
    k_select_gather<<<B_, 256>>>(ent, wpe, x0);

    // 7) cross-attention layers
    for (int i = 0; i < NLAY; i++){
        k_sgemm<false><<<dim3(2,2,B_), 256>>>(wpe, 256, 65536, Wk + (size_t)i*65536, 256, 0,
                                              bk + i*256, Kb, 256, 65536, 256);
        k_sgemm<false><<<dim3(2,2,B_), 256>>>(wpe, 256, 65536, Wv + (size_t)i*65536, 256, 0,
                                              bv + i*256, Vb, 256, 65536, 256);
        const float* xin = (i == 1) ? x1 : x0;
        float* xout = (i == 0) ? x1 : ((i == 1) ? x0 : out_phrase);
        k_attn<<<B_*NH, 256>>>(xin, Wq + (size_t)i*65536, bq + i*256, Kb, Vb,
                               O, (i == NLAY-1) ? attn3 : nullptr);
        k_post<<<B_*NP, 256>>>(xin, O,
                               out_w + (size_t)i*65536, out_b + i*256,
                               ln0_g + i*256, ln0_b + i*256,
                               lin_w + (size_t)i*65536, lin_b + i*256,
                               ln1_g + i*256, ln1_b + i*256, xout);
    }

    // 8) slot_sim (mean over heads, last layer) and eos broadcast
    k_slot_sim<<<B_*NP*LW/256, 256>>>(attn3, out_slotsim);
    k_eos<<<B_, 256>>>(eos_slot, out_eos);
}

// round 13
// speedup vs baseline: 1.2549x; 1.2549x over previous
#include <cuda_runtime.h>
#include <cuda_bf16.h>
#include <math.h>

// ---------------- problem constants ----------------
#define B_   128
#define C_   256
#define LW   256     // words = L-1
#define T_   1024
#define NH   8
#define NP   8
#define NLAY 3

// ---------------- scratch (device globals; no runtime allocation) ----------------
__device__ float g_word_pe[B_*LW*C_];        // 32 MB
__device__ float g_wp     [B_*LW*C_];        // 32 MB
__device__ float g_vproj  [B_*T_*C_];        // 128 MB
__device__ float g_sim    [B_*LW*T_];        // 128 MB
__device__ float g_entropy[B_*LW];
__device__ float g_Kbuf   [NLAY*B_*LW*C_];   // 96 MB (all layers)
__device__ float g_Vbuf   [NLAY*B_*LW*C_];   // 96 MB (all layers)
__device__ float g_Wq[NLAY*C_*C_];
__device__ float g_Wk[NLAY*C_*C_];
__device__ float g_Wv[NLAY*C_*C_];
__device__ float g_bq[NLAY*C_];
__device__ float g_bk[NLAY*C_];
__device__ float g_bv[NLAY*C_];
__device__ float g_x0[B_*NP*C_];
__device__ float g_x1[B_*NP*C_];
__device__ float g_O [B_*NP*C_];
__device__ float g_attn3[B_*NH*NP*LW];       // 2 MB (last-layer attn for slot_sim)

// ---------------- packed f32x2 helpers (sm_103a FFMA2 path) ----------------
__device__ __forceinline__ unsigned long long dup2(float a){
    unsigned long long d; asm("mov.b64 %0, {%1, %1};" : "=l"(d) : "f"(a)); return d;
}
__device__ __forceinline__ void ffma2(unsigned long long& d, unsigned long long a, unsigned long long b){
    asm("fma.rn.f32x2 %0, %1, %2, %0;" : "+l"(d) : "l"(a), "l"(b));
}
__device__ __forceinline__ float2 unpack2(unsigned long long v){
    float2 r; asm("mov.b64 {%0, %1}, %2;" : "=f"(r.x), "=f"(r.y) : "l"(v)); return r;
}

// ---------------- reduction helpers ----------------
__device__ __forceinline__ float warpSum(float v){
#pragma unroll
    for (int o = 16; o > 0; o >>= 1) v += __shfl_xor_sync(0xffffffffu, v, o);
    return v;
}
__device__ __forceinline__ float warpMax(float v){
#pragma unroll
    for (int o = 16; o > 0; o >>= 1) v = fmaxf(v, __shfl_xor_sync(0xffffffffu, v, o));
    return v;
}
__device__ __forceinline__ float blockSum256(float v, float* sh){
    int lane = threadIdx.x & 31, w = threadIdx.x >> 5;
    v = warpSum(v);
    __syncthreads();
    if (lane == 0) sh[w] = v;
    __syncthreads();
    float t = sh[0];
#pragma unroll
    for (int i = 1; i < 8; i++) t += sh[i];
    return t;
}
__device__ __forceinline__ float blockMax256(float v, float* sh){
    int lane = threadIdx.x & 31, w = threadIdx.x >> 5;
    v = warpMax(v);
    __syncthreads();
    if (lane == 0) sh[w] = v;
    __syncthreads();
    float t = sh[0];
#pragma unroll
    for (int i = 1; i < 8; i++) t = fmaxf(t, sh[i]);
    return t;
}

// ---------------- word_pe = txt_emb[:,1:] + sine positional ----------------
__global__ void k_word_pe(const float* __restrict__ txt_emb, float* __restrict__ wpe){
    int idx = blockIdx.x * 256 + threadIdx.x;   // B_*LW*C_ total
    int c = idx & 255;
    int l = (idx >> 8) & 255;
    int b = idx >> 16;
    float x = (float)(l + 1);
    float expo = (float)(c & ~1) * (1.0f / 256.0f);
    float d = expf(expo * 9.210340371976184f);  // 10000^(2*floor(c/2)/256)
    float arg = x / d;
    float pe = (c & 1) ? cosf(arg) : sinf(arg);
    wpe[idx] = txt_emb[((size_t)b * 257 + (l + 1)) * 256 + c] + pe;
}

// ---------------- shared SGEMM body: 128x128 tile, K multiple of 8 ----------------
// Mainloop uses packed f32x2 FFMA (2 FLOP/lane/instr).
template<bool TRANSB>
__device__ __forceinline__ void sgemm_body(
    const float* __restrict__ Ab, int lda,
    const float* __restrict__ Bb, int ldb,
    const float* __restrict__ bias,
    float* __restrict__ Cb, int ldc, int K, int ntile)
{
    __shared__ float As[8][128];
    __shared__ float Bs[8][128];
    const int tid = threadIdx.x;

    const int arow = tid >> 1;            // 0..127
    const int acol = (tid & 1) * 4;       // 0 or 4
    const int brow = tid >> 5;            // 0..7   (NN)
    const int bcol = (tid & 31) * 4;      // 0..124 (NN)
    const int tx = (tid & 15) * 4;        // col base
    const int ty = (tid >> 4) * 4;        // row base

    unsigned long long acc[8][4];
#pragma unroll
    for (int i = 0; i < 8; i++)
#pragma unroll
        for (int j = 0; j < 4; j++) acc[i][j] = 0ull;

    // prologue: first k-tile into registers
    float4 av = *(const float4*)(Ab + (long long)arow * lda + acol);
    float4 bv;
    if (TRANSB) bv = *(const float4*)(Bb + (long long)(ntile + arow) * ldb + acol);
    else        bv = *(const float4*)(Bb + (long long)brow * ldb + ntile + bcol);

    for (int k0 = 0; k0 < K; k0 += 8){
        As[acol+0][arow] = av.x; As[acol+1][arow] = av.y;
        As[acol+2][arow] = av.z; As[acol+3][arow] = av.w;
        if (TRANSB){
            Bs[acol+0][arow] = bv.x; Bs[acol+1][arow] = bv.y;
            Bs[acol+2][arow] = bv.z; Bs[acol+3][arow] = bv.w;
        } else {
            *(float4*)(&Bs[brow][bcol]) = bv;
        }
        __syncthreads();

        const int kn = k0 + 8;
        if (kn < K){
            av = *(const float4*)(Ab + (long long)arow * lda + kn + acol);
            if (TRANSB) bv = *(const float4*)(Bb + (long long)(ntile + arow) * ldb + kn + acol);
            else        bv = *(const float4*)(Bb + (long long)(kn + brow) * ldb + ntile + bcol);
        }

#pragma unroll
        for (int k = 0; k < 8; k++){
            float4 aA = *(const float4*)(&As[k][ty]);
            float4 aB = *(const float4*)(&As[k][ty + 64]);
            ulonglong2 bA = *(const ulonglong2*)(&Bs[k][tx]);        // pairs (b0,b1),(b2,b3)
            ulonglong2 bB = *(const ulonglong2*)(&Bs[k][tx + 64]);   // pairs (b4,b5),(b6,b7)
            float a8[8] = {aA.x, aA.y, aA.z, aA.w, aB.x, aB.y, aB.z, aB.w};
#pragma unroll
            for (int i = 0; i < 8; i++){
                unsigned long long ad = dup2(a8[i]);
                ffma2(acc[i][0], ad, bA.x);
                ffma2(acc[i][1], ad, bA.y);
                ffma2(acc[i][2], ad, bB.x);
                ffma2(acc[i][3], ad, bB.y);
            }
        }
        __syncthreads();
    }

    float bvals[8];
    if (bias){
#pragma unroll
        for (int j = 0; j < 4; j++){ bvals[j] = bias[ntile + tx + j]; bvals[j+4] = bias[ntile + tx + 64 + j]; }
    } else {
#pragma unroll
        for (int j = 0; j < 8; j++) bvals[j] = 0.f;
    }
#pragma unroll
    for (int i = 0; i < 8; i++){
        int m = (i < 4) ? (ty + i) : (ty + 64 + (i - 4));
        float* cp = Cb + (long long)m * ldc;
        float2 p0 = unpack2(acc[i][0]);
        float2 p1 = unpack2(acc[i][1]);
        float2 p2 = unpack2(acc[i][2]);
        float2 p3 = unpack2(acc[i][3]);
        float4 v0 = make_float4(p0.x+bvals[0], p0.y+bvals[1], p1.x+bvals[2], p1.y+bvals[3]);
        float4 v1 = make_float4(p2.x+bvals[4], p2.y+bvals[5], p3.x+bvals[6], p3.y+bvals[7]);
        *(float4*)(cp + tx)      = v0;
        *(float4*)(cp + tx + 64) = v1;
    }
}

// ---------------- generic batched SGEMM wrapper ----------------
template<bool TRANSB>
__global__ void __launch_bounds__(256, 2) k_sgemm(
    const float* __restrict__ A, int lda, long long sA,
    const float* __restrict__ B, int ldb, long long sB,
    const float* __restrict__ bias,
    float* __restrict__ C, int ldc, long long sC, int K)
{
    const int ntile = blockIdx.x * 128;
    const float* Ab = A + (long long)blockIdx.z * sA + (long long)(blockIdx.y * 128) * lda;
    const float* Bb = B + (long long)blockIdx.z * sB;
    float*       Cb = C + (long long)blockIdx.z * sC + (long long)(blockIdx.y * 128) * ldc + ntile;
    sgemm_body<TRANSB>(Ab, lda, Bb, ldb, bias, Cb, ldc, K, ntile);
}

// ---------------- batched weight folds: z -> (layer, type) ----------------
__global__ void __launch_bounds__(256, 2) k_sgemm_fold(
    const float* __restrict__ q_w, const float* __restrict__ kv_w,
    const float* __restrict__ in_w,
    float* __restrict__ Wq, float* __restrict__ Wk, float* __restrict__ Wv)
{
    int z = blockIdx.z, layer = z / 3, type = z % 3;
    const float* A; int lda;
    if (type == 0){ A = q_w  + (size_t)layer * 65536;        lda = 256; }
    else if (type == 1){ A = kv_w + (size_t)layer * 131072;        lda = 512; }
    else            { A = kv_w + (size_t)layer * 131072 + 256;  lda = 512; }
    const float* Bm = in_w + (size_t)layer * 196608 + type * 256;   // ldb 768
    float* Cm = ((type == 0) ? Wq : (type == 1) ? Wk : Wv) + (size_t)layer * 65536;
    int ntile = blockIdx.x * 128;
    sgemm_body<false>(A + (long long)(blockIdx.y * 128) * lda, lda, Bm, 768, nullptr,
                      Cm + (long long)(blockIdx.y * 128) * 256 + ntile, 256, 256, ntile);
}

// ---------------- batched K/V projection for all layers: z -> (kv, layer, b) ----------------
__global__ void __launch_bounds__(256, 2) k_sgemm_kv(
    const float* __restrict__ wpe,
    const float* __restrict__ Wk, const float* __restrict__ Wv,
    const float* __restrict__ bk, const float* __restrict__ bv,
    float* __restrict__ Kall, float* __restrict__ Vall)
{
    int z = blockIdx.z;                  // 0 .. 6*B_-1
    int kv = z / (NLAY * B_);            // 0 = K, 1 = V
    int layer = (z / B_) % NLAY;
    int b = z % B_;
    const float* W  = (kv ? Wv : Wk) + (size_t)layer * 65536;
    const float* bb = (kv ? bv : bk) + layer * 256;
    float* Cc = (kv ? Vall : Kall) + ((size_t)layer * B_ + b) * 65536;
    int ntile = blockIdx.x * 128;
    sgemm_body<false>(wpe + (size_t)b * 65536 + (long long)(blockIdx.y * 128) * 256, 256,
                      W, 256, bb,
                      Cc + (long long)(blockIdx.y * 128) * 256 + ntile, 256, 256, ntile);
}

// ---------------- combined biases: b' = b_small @ in_w_slice + in_b_slice ----------------
__global__ void k_bias_combine(const float* __restrict__ q_b, const float* __restrict__ kv_b,
                               const float* __restrict__ in_w, const float* __restrict__ in_b,
                               float* __restrict__ bq, float* __restrict__ bk, float* __restrict__ bv)
{
    int i = blockIdx.x / 3, type = blockIdx.x % 3;
    int c = threadIdx.x;
    const float* inw = in_w + (size_t)i * 256 * 768;
    const float* inb = in_b + (size_t)i * 768;
    float acc;
    if (type == 0){
        acc = inb[c];
        for (int j = 0; j < 256; j++) acc += q_b[i*256 + j] * inw[j*768 + c];
        bq[i*256 + c] = acc;
    } else if (type == 1){
        acc = inb[256 + c];
        for (int j = 0; j < 256; j++) acc += kv_b[i*512 + j] * inw[j*768 + 256 + c];
        bk[i*256 + c] = acc;
    } else {
        acc = inb[512 + c];
        for (int j = 0; j < 256; j++) acc += kv_b[i*512 + 256 + j] * inw[j*768 + 512 + c];
        bv[i*256 + c] = acc;
    }
}

// ---------------- fused softmax over T + entropy (row = b*LW + l) ----------------
__global__ void __launch_bounds__(256) k_softmax_entropy(
    const float* __restrict__ sim, float* __restrict__ attn, float* __restrict__ ent)
{
    __shared__ float sh[8];
    int row = blockIdx.x;
    int t = threadIdx.x;
    const float4 v = ((const float4*)(sim + (size_t)row * 1024))[t];
    float m = fmaxf(fmaxf(v.x, v.y), fmaxf(v.z, v.w));
    m = blockMax256(m, sh);
    float ex = expf(v.x - m), ey = expf(v.y - m), ez = expf(v.z - m), ew = expf(v.w - m);
    float s = blockSum256(ex + ey + ez + ew, sh);
    float inv = 1.0f / s;
    float4 p = make_float4(ex*inv, ey*inv, ez*inv, ew*inv);
    ((float4*)(attn + (size_t)row * 1024))[t] = p;
    float e = p.x * logf(p.x + 1e-6f) + p.y * logf(p.y + 1e-6f)
            + p.z * logf(p.z + 1e-6f) + p.w * logf(p.w + 1e-6f);
    e = blockSum256(e, sh);
    if (t == 0) ent[row] = -e;
}

// ---------------- per-batch selection (stable desc sort + greedy) + gather ----------------
__global__ void __launch_bounds__(256) k_select_gather(
    const float* __restrict__ ent, const float* __restrict__ wpe, float* __restrict__ x0)
{
    __shared__ unsigned long long key[256];
    __shared__ int ssel[NP];
    int b = blockIdx.x;
    int t = threadIdx.x;
    float s = ent[b*256 + t];
    unsigned u = __float_as_uint(s);
    u = (u & 0x80000000u) ? ~u : (u ^ 0x80000000u);           // ascending-monotonic
    key[t] = ((unsigned long long)(~u) << 32) | (unsigned long long)t;  // asc sort => desc score, ties asc idx
    __syncthreads();
    for (int k = 2; k <= 256; k <<= 1){
        for (int j = k >> 1; j > 0; j >>= 1){
            int ixj = t ^ j;
            if (ixj > t){
                unsigned long long a = key[t], c2 = key[ixj];
                bool up = ((t & k) == 0);
                if ((a > c2) == up){ key[t] = c2; key[ixj] = a; }
            }
            __syncthreads();
        }
    }
    if (t == 0){
        int sel[NP]; int cnt = 0;
        for (int r = 0; r < 256 && cnt < NP; r++){
            int idx = (int)(key[r] & 0xffffffffULL);
            bool ok = true;
            for (int j2 = 0; j2 < cnt; j2++){
                int dd = idx - sel[j2]; if (dd < 0) dd = -dd;
                if (dd < 2){ ok = false; break; }
            }
            if (ok) sel[cnt++] = idx;
        }
        int last = sel[(cnt > 0) ? cnt - 1 : 0];
        for (int p = 0; p < NP; p++) ssel[p] = (p < cnt) ? sel[p] : last;
    }
    __syncthreads();
    for (int i = t; i < NP*C_; i += 256){
        int p = i >> 8, cc = i & 255;
        x0[(size_t)b * NP * C_ + i] = wpe[((size_t)b * 256 + ssel[p]) * 256 + cc];
    }
}

// ---------------- attention per (b,h): Q-proj + scores + softmax + O ----------------
__global__ void __launch_bounds__(256) k_attn(
    const float* __restrict__ x, const float* __restrict__ Wq, const float* __restrict__ bq,
    const float* __restrict__ Kb, const float* __restrict__ Vb,
    float* __restrict__ O, float* __restrict__ attn3)
{
    __shared__ float sXV[8192];
    __shared__ float sQ[NP*32];
    __shared__ float sS[NP*256];
    int blk = blockIdx.x;
    int b = blk >> 3, h = blk & 7;
    int tid = threadIdx.x;
    for (int i = tid; i < NP*C_; i += 256) sXV[i] = x[(size_t)b * NP * C_ + i];
    __syncthreads();
    int q = tid >> 5, d = tid & 31;
    int col = h * 32 + d;
    float acc = bq[col];
#pragma unroll 4
    for (int j = 0; j < 256; j++) acc += sXV[q*256 + j] * Wq[j*256 + col];
    __syncthreads();
    sQ[q*32 + d] = acc * 0.17677669529663687f;   // 1/sqrt(32)
    __syncthreads();
    const float* Kp = Kb + (size_t)b * LW * C_;
    const float* Vp = Vb + (size_t)b * LW * C_;
    for (int i = tid; i < LW*32; i += 256){
        int r = i >> 5, cc = i & 31;
        sXV[i] = Vp[r*256 + h*32 + cc];
    }
    {   // scores: thread = key index
        int k = tid;
        const float4* kp = (const float4*)(Kp + (size_t)k * 256 + h * 32);
        float4 kr[8];
#pragma unroll
        for (int j = 0; j < 8; j++) kr[j] = kp[j];
#pragma unroll
        for (int qq = 0; qq < NP; qq++){
            const float4* qp4 = (const float4*)(sQ + qq * 32);
            float sc = 0.f;
#pragma unroll
            for (int j = 0; j < 8; j++){
                float4 qv = qp4[j];
                sc += qv.x*kr[j].x + qv.y*kr[j].y + qv.z*kr[j].z + qv.w*kr[j].w;
            }
            sS[qq*256 + k] = sc;
        }
    }
    __syncthreads();
    {   // softmax over k: warp q owns row q
        float m = -INFINITY;
#pragma unroll
        for (int k = d; k < 256; k += 32) m = fmaxf(m, sS[q*256 + k]);
        m = warpMax(m);
        float sum = 0.f;
#pragma unroll
        for (int k = d; k < 256; k += 32){ float e = expf(sS[q*256 + k] - m); sS[q*256 + k] = e; sum += e; }
        sum = warpSum(sum);
        float inv = 1.0f / sum;
#pragma unroll
        for (int k = d; k < 256; k += 32) sS[q*256 + k] *= inv;
    }
    __syncthreads();
    float o_ = 0.f;
#pragma unroll 8
    for (int k = 0; k < 256; k++) o_ += sS[q*256 + k] * sXV[k*32 + d];
    O[(size_t)b * NP * C_ + q * 256 + col] = o_;
    if (attn3){
        int k = tid;
#pragma unroll
        for (int qq = 0; qq < NP; qq++)
            attn3[(size_t)b * (NH*NP*LW) + h * (NP*LW) + qq * LW + k] = sS[qq*256 + k];
    }
}

// ---------------- per-row: out-proj + residual + LN + FFN(relu) + residual + LN ----------------
__global__ void __launch_bounds__(256) k_post(
    const float* __restrict__ x, const float* __restrict__ O,
    const float* __restrict__ ow, const float* __restrict__ ob,
    const float* __restrict__ g0, const float* __restrict__ b0,
    const float* __restrict__ lw, const float* __restrict__ lb,
    const float* __restrict__ g1, const float* __restrict__ b1,
    float* __restrict__ xout)
{
    __shared__ float sO[256];
    __shared__ float sX1[256];
    __shared__ float sh[8];
    int row = blockIdx.x;
    int c = threadIdx.x;
    sO[c] = O[(size_t)row * 256 + c];
    float xv = x[(size_t)row * 256 + c];
    __syncthreads();
    float acc = ob[c];
#pragma unroll 4
    for (int j = 0; j < 256; j++) acc += sO[j] * ow[j*256 + c];
    float a = xv + acc;
    float mu = blockSum256(a, sh) * (1.0f/256.0f);
    float tdev = a - mu;
    float var = blockSum256(tdev*tdev, sh) * (1.0f/256.0f);
    float x1 = tdev * rsqrtf(var + 1e-5f) * g0[c] + b0[c];
    sX1[c] = x1;
    __syncthreads();
    float u = lb[c];
#pragma unroll 4
    for (int j = 0; j < 256; j++) u += sX1[j] * lw[j*256 + c];
    u = fmaxf(u, 0.0f);
    float a2 = x1 + u;
    float mu2 = blockSum256(a2, sh) * (1.0f/256.0f);
    float t2 = a2 - mu2;
    float var2 = blockSum256(t2*t2, sh) * (1.0f/256.0f);
    xout[(size_t)row * 256 + c] = t2 * rsqrtf(var2 + 1e-5f) * g1[c] + b1[c];
}

// ---------------- slot_sim = mean over heads of last-layer attn ----------------
__global__ void k_slot_sim(const float* __restrict__ attn3, float* __restrict__ out){
    int idx = blockIdx.x * 256 + threadIdx.x;
    int b = idx >> 11;
    int r = idx & 2047;
    float s = 0.f;
#pragma unroll
    for (int h = 0; h < NH; h++) s += attn3[(size_t)b * (NH*NP*LW) + h * (NP*LW) + r];
    out[idx] = s * (1.0f / NH);
}

// ---------------- eos broadcast ----------------
__global__ void k_eos(const float* __restrict__ eos, float* __restrict__ out){
    out[blockIdx.x * 256 + threadIdx.x] = eos[threadIdx.x];
}

// ================= host launcher =================
extern "C" void kernel_launch(void* const* d_in, const int* in_sizes, int n_in,
                              void* d_out, int out_size)
{
    const float* txt_emb      = (const float*)d_in[0];
    const float* video_feats  = (const float*)d_in[2];
    const float* word_proj_w  = (const float*)d_in[4];
    const float* word_proj_b  = (const float*)d_in[5];
    const float* video_proj_w = (const float*)d_in[6];
    const float* video_proj_b = (const float*)d_in[7];
    const float* q_w   = (const float*)d_in[8];
    const float* q_b   = (const float*)d_in[9];
    const float* kv_w  = (const float*)d_in[10];
    const float* kv_b  = (const float*)d_in[11];
    const float* in_w  = (const float*)d_in[12];
    const float* in_b  = (const float*)d_in[13];
    const float* out_w = (const float*)d_in[14];
    const float* out_b = (const float*)d_in[15];
    const float* ln0_g = (const float*)d_in[16];
    const float* ln0_b = (const float*)d_in[17];
    const float* lin_w = (const float*)d_in[18];
    const float* lin_b = (const float*)d_in[19];
    const float* ln1_g = (const float*)d_in[20];
    const float* ln1_b = (const float*)d_in[21];
    const float* eos_slot = (const float*)d_in[22];

    float *wpe, *wp, *vproj, *sim, *ent, *Kb, *Vb, *Wq, *Wk, *Wv, *bq, *bk, *bv, *x0, *x1, *O, *attn3;
    cudaGetSymbolAddress((void**)&wpe,   g_word_pe);
    cudaGetSymbolAddress((void**)&wp,    g_wp);
    cudaGetSymbolAddress((void**)&vproj, g_vproj);
    cudaGetSymbolAddress((void**)&sim,   g_sim);
    cudaGetSymbolAddress((void**)&ent,   g_entropy);
    cudaGetSymbolAddress((void**)&Kb,    g_Kbuf);
    cudaGetSymbolAddress((void**)&Vb,    g_Vbuf);
    cudaGetSymbolAddress((void**)&Wq,    g_Wq);
    cudaGetSymbolAddress((void**)&Wk,    g_Wk);
    cudaGetSymbolAddress((void**)&Wv,    g_Wv);
    cudaGetSymbolAddress((void**)&bq,    g_bq);
    cudaGetSymbolAddress((void**)&bk,    g_bk);
    cudaGetSymbolAddress((void**)&bv,    g_bv);
    cudaGetSymbolAddress((void**)&x0,    g_x0);
    cudaGetSymbolAddress((void**)&x1,    g_x1);
    cudaGetSymbolAddress((void**)&O,     g_O);
    cudaGetSymbolAddress((void**)&attn3, g_attn3);

    float* out = (float*)d_out;
    float* out_phrase  = out;                         // [128,8,256]
    float* out_attn    = out + 262144;                // [128,256,1024]
    float* out_slotsim = out + 33816576;              // [128,8,256]
    float* out_eos     = out + 34078720;              // [128,1,256]

    // 1) word positional embedding
    k_word_pe<<<B_*LW*C_/256, 256>>>(txt_emb, wpe);

    // 2) ALL 9 weight folds in one launch (concurrent, one wave)
    k_sgemm_fold<<<dim3(2,2,9), 256>>>(q_w, kv_w, in_w, Wq, Wk, Wv);
    k_bias_combine<<<9, 256>>>(q_b, kv_b, in_w, in_b, bq, bk, bv);

    // 3) K/V projections for ALL layers, one launch
    k_sgemm_kv<<<dim3(2,2,2*NLAY*B_), 256>>>(wpe, Wk, Wv, bk, bv, Kb, Vb);

    // 4) projections
    k_sgemm<false><<<dim3(2,2,B_), 256>>>(wpe, 256, 65536, word_proj_w, 256, 0, word_proj_b,
                                          wp, 256, 65536, 256);
    k_sgemm<false><<<dim3(2,8,B_), 256>>>(video_feats, 256, 262144, video_proj_w, 256, 0, video_proj_b,
                                          vproj, 256, 262144, 256);

    // 5) sim = wp @ vproj^T   (NT)
    k_sgemm<true><<<dim3(8,2,B_), 256>>>(wp, 256, 65536, vproj, 256, 262144, nullptr,
                                         sim, 1024, 262144, 256);

    // 6) softmax over T -> attn output, entropy
    k_softmax_entropy<<<B_*LW, 256>>>(sim, out_attn, ent);

    // 7) selection + gather phrase slots
    k_select_gather<<<B_, 256>>>(ent, wpe, x0);

    // 8) cross-attention layers (K/V precomputed)
    for (int i = 0; i < NLAY; i++){
        const float* xin = (i == 1) ? x1 : x0;
        float* xout = (i == 0) ? x1 : ((i == 1) ? x0 : out_phrase);
        k_attn<<<B_*NH, 256>>>(xin, Wq + (size_t)i*65536, bq + i*256,
                               Kb + (size_t)i*B_*65536, Vb + (size_t)i*B_*65536,
                               O, (i == NLAY-1) ? attn3 : nullptr);
        k_post<<<B_*NP, 256>>>(xin, O,
                               out_w + (size_t)i*65536, out_b + i*256,
                               ln0_g + i*256, ln0_b + i*256,
                               lin_w + (size_t)i*65536, lin_b + i*256,
                               ln1_g + i*256, ln1_b + i*256, xout);
    }

    // 9) slot_sim (mean over heads, last layer) and eos broadcast
    k_slot_sim<<<B_*NP*LW/256, 256>>>(attn3, out_slotsim);
    k_eos<<<B_, 256>>>(eos_slot, out_eos);
}